// round 4
// baseline (speedup 1.0000x reference)
#include <cuda_runtime.h>
#include <cuda_bf16.h>
#include <cstdint>

#define FULLMASK 0xFFFFFFFFu

// ======================= device scratch (no allocs allowed) =======================
// M: 179 blocks x 128 rows x 128 cols (bf16)        = 5.9 MB
// Zb: z in bf16 (2048 x 128)                         = 0.5 MB
// V: per-sample deltas, [22912 rows][2048 samples]   = 93.8 MB (bf16)
// H1T/H2T: hidden activations transposed [128][2048] = 1 MB each (fp32)
__device__ __align__(16) __nv_bfloat16 g_Mb[22912u * 128u];
__device__ __align__(16) __nv_bfloat16 g_Zb[2048u * 128u];
__device__ __align__(16) __nv_bfloat16 g_V [22912u * 2048u];
__device__ __align__(16) float g_H1T[128u * 2048u];
__device__ __align__(16) float g_H2T[128u * 2048u];

__device__ __forceinline__ uint32_t smem_u32(const void* p) {
    uint32_t a;
    asm("{ .reg .u64 t; cvta.to.shared.u64 t, %1; cvt.u32.u64 %0, t; }" : "=r"(a) : "l"(p));
    return a;
}

// ======================= FWHT (contiguous layout) =======================
__device__ __forceinline__ void fwht128c(float &u0, float &u1, float &u2, float &u3, int lane) {
    float a0 = u0 + u1, a1 = u0 - u1;
    float a2 = u2 + u3, a3 = u2 - u3;
    u0 = a0 + a2; u2 = a0 - a2;
    u1 = a1 + a3; u3 = a1 - a3;
#pragma unroll
    for (int m = 1; m <= 16; m <<= 1) {
        float s = (lane & m) ? -1.0f : 1.0f;
        float p0 = __shfl_xor_sync(FULLMASK, u0, m);
        float p1 = __shfl_xor_sync(FULLMASK, u1, m);
        float p2 = __shfl_xor_sync(FULLMASK, u2, m);
        float p3 = __shfl_xor_sync(FULLMASK, u3, m);
        u0 = fmaf(s, u0, p0); u1 = fmaf(s, u1, p1);
        u2 = fmaf(s, u2, p2); u3 = fmaf(s, u3, p3);
    }
}

// ======================= K1: build M rows (bf16) + convert z to bf16 ==============
// Row m of M_r = (ffS[r,m]/128) * ffB[r,:] * H( scatter_P( ffG[r,:] * H[:,m] ) )
// H[e,m] = (-1)^popc(e&m). One warp per row; 2864 M-blocks + 64 zconv-blocks.
__global__ __launch_bounds__(256)
void k1_build(const float* __restrict__ z,
              const float* __restrict__ ffB, const float* __restrict__ ffG,
              const float* __restrict__ ffS, const int* __restrict__ ffP)
{
    __shared__ __align__(16) float sstg[8][128];
    const int tid = threadIdx.x, w = tid >> 5, lane = tid & 31;

    if (blockIdx.x >= 2864) {
        // z (fp32) -> Zb (bf16): 65536 float4 chunks over 64 blocks * 256 thr * 4
        int gt = (blockIdx.x - 2864) * 256 + tid;
        const float4* zf4 = reinterpret_cast<const float4*>(z);
        uint2* zb2 = reinterpret_cast<uint2*>(g_Zb);
#pragma unroll
        for (int it = 0; it < 4; it++) {
            int i = gt * 4 + it;
            float4 v = zf4[i];
            __nv_bfloat162 lo = __float22bfloat162_rn(make_float2(v.x, v.y));
            __nv_bfloat162 hi = __float22bfloat162_rn(make_float2(v.z, v.w));
            uint2 o;
            o.x = *reinterpret_cast<uint32_t*>(&lo);
            o.y = *reinterpret_cast<uint32_t*>(&hi);
            zb2[i] = o;
        }
        return;
    }

    const int rowid = blockIdx.x * 8 + w;       // 0..22911
    const int r = rowid >> 7, m = rowid & 127;
    const int o = r * 128;

    float4 g4 = reinterpret_cast<const float4*>(ffG + o)[lane];
    float4 b4 = reinterpret_cast<const float4*>(ffB + o)[lane];
    int4   p4 = reinterpret_cast<const int4*>(ffP + o)[lane];
    float  sm = ffS[o + m] * (1.0f / 128.0f);

    // t = g * H[:,m]
    int e = lane << 2;
    float t0 = (__popc((e + 0) & m) & 1) ? -g4.x : g4.x;
    float t1 = (__popc((e + 1) & m) & 1) ? -g4.y : g4.y;
    float t2 = (__popc((e + 2) & m) & 1) ? -g4.z : g4.z;
    float t3 = (__popc((e + 3) & m) & 1) ? -g4.w : g4.w;

    // scatter via P^T : stg[p[j]] = t[j]
    float* stg = sstg[w];
    stg[p4.x] = t0; stg[p4.y] = t1; stg[p4.z] = t2; stg[p4.w] = t3;
    __syncwarp();
    float4 u = *reinterpret_cast<float4*>(stg + e);
    fwht128c(u.x, u.y, u.z, u.w, lane);

    float o0 = sm * b4.x * u.x, o1 = sm * b4.y * u.y;
    float o2 = sm * b4.z * u.z, o3 = sm * b4.w * u.w;
    __nv_bfloat162 lo = __float22bfloat162_rn(make_float2(o0, o1));
    __nv_bfloat162 hi = __float22bfloat162_rn(make_float2(o2, o3));
    uint2 ov;
    ov.x = *reinterpret_cast<uint32_t*>(&lo);
    ov.y = *reinterpret_cast<uint32_t*>(&hi);
    reinterpret_cast<uint2*>(g_Mb + (size_t)rowid * 128)[lane] = ov;
}

// ======================= K2: V = M @ Z^T via mma.sync (HMMA bf16) =================
// Grid (179, 16). CTA: A = M_r (128x128), B = Z[s0:s0+128] (128x128). 8 warps as
// 2(M) x 4(N); warp tile 64x32. A row-major (.row), Z rows are .col B directly.
// smem: XOR-swizzled 16B chunks — row stride 256B, chunk ch stored at ch^(row&7).
#define SWZ(row, ch) ((uint32_t)((row) * 256 + (((ch) ^ ((row) & 7)) << 4)))

__device__ __forceinline__ void ldmx4(uint32_t &r0, uint32_t &r1, uint32_t &r2, uint32_t &r3, uint32_t a) {
    asm volatile("ldmatrix.sync.aligned.m8n8.x4.shared.b16 {%0,%1,%2,%3}, [%4];"
                 : "=r"(r0), "=r"(r1), "=r"(r2), "=r"(r3) : "r"(a));
}
__device__ __forceinline__ void ldmx2(uint32_t &r0, uint32_t &r1, uint32_t a) {
    asm volatile("ldmatrix.sync.aligned.m8n8.x2.shared.b16 {%0,%1}, [%2];"
                 : "=r"(r0), "=r"(r1) : "r"(a));
}
__device__ __forceinline__ void mma_bf16(float c[4], const uint32_t a[4], const uint32_t b[2]) {
    asm volatile(
        "mma.sync.aligned.m16n8k16.row.col.f32.bf16.bf16.f32 "
        "{%0,%1,%2,%3}, {%4,%5,%6,%7}, {%8,%9}, {%0,%1,%2,%3};"
        : "+f"(c[0]), "+f"(c[1]), "+f"(c[2]), "+f"(c[3])
        : "r"(a[0]), "r"(a[1]), "r"(a[2]), "r"(a[3]), "r"(b[0]), "r"(b[1]));
}

__global__ __launch_bounds__(256)
void k2_gemm()
{
    extern __shared__ char smem[];
    const int tid = threadIdx.x, w = tid >> 5, lane = tid & 31;
    const int r = blockIdx.x;
    const int s0 = blockIdx.y * 128;

    // fill A (chunks 0..2047) and B (2048..4095)
    const uint4* srcA = reinterpret_cast<const uint4*>(g_Mb + (size_t)r * 16384);
    const uint4* srcB = reinterpret_cast<const uint4*>(g_Zb + (size_t)s0 * 128);
#pragma unroll
    for (int it = 0; it < 16; it++) {
        int c = it * 256 + tid;
        int cc = c & 2047;
        int row = cc >> 4, ch = cc & 15;
        uint4 val = (c < 2048) ? srcA[cc] : srcB[cc];
        uint32_t off = SWZ(row, ch) + ((c < 2048) ? 0u : 32768u);
        *reinterpret_cast<uint4*>(smem + off) = val;
    }
    __syncthreads();

    const uint32_t sbA = smem_u32(smem);
    const uint32_t sbB = sbA + 32768;
    const int wm = w & 1, wn = w >> 1;
    const int mbase = wm * 64, nbase = wn * 32;

    float acc[4][4][4];
#pragma unroll
    for (int mt = 0; mt < 4; mt++)
#pragma unroll
        for (int nt = 0; nt < 4; nt++)
#pragma unroll
            for (int q = 0; q < 4; q++) acc[mt][nt][q] = 0.0f;

    const int arow_off = lane & 15;          // row within 16-row tile
    const int ach_off  = lane >> 4;          // 0/1 -> k chunk
    const int brow_off = lane & 7;
    const int bch_off  = (lane >> 3) & 1;

#pragma unroll
    for (int ks = 0; ks < 8; ks++) {
        const int k0c = ks * 2;
        uint32_t a[4][4];
#pragma unroll
        for (int mt = 0; mt < 4; mt++) {
            uint32_t ad = sbA + SWZ(mbase + mt * 16 + arow_off, k0c + ach_off);
            ldmx4(a[mt][0], a[mt][1], a[mt][2], a[mt][3], ad);
        }
        uint32_t b[4][2];
#pragma unroll
        for (int nt = 0; nt < 4; nt++) {
            uint32_t bd = sbB + SWZ(nbase + nt * 8 + brow_off, k0c + bch_off);
            ldmx2(b[nt][0], b[nt][1], bd);
        }
#pragma unroll
        for (int mt = 0; mt < 4; mt++)
#pragma unroll
            for (int nt = 0; nt < 4; nt++)
                mma_bf16(acc[mt][nt], a[mt], b[nt]);
    }

    // epilogue: c0,c1 -> (m = lane>>2, n = 2*(lane&3)+{0,1}); c2,c3 -> m+8
    const int ml = lane >> 2, nl = 2 * (lane & 3);
#pragma unroll
    for (int mt = 0; mt < 4; mt++) {
#pragma unroll
        for (int nt = 0; nt < 4; nt++) {
            int gm = r * 128 + mbase + mt * 16 + ml;
            int gn = s0 + nbase + nt * 8 + nl;
            __nv_bfloat162 v0 = __float22bfloat162_rn(make_float2(acc[mt][nt][0], acc[mt][nt][1]));
            __nv_bfloat162 v1 = __float22bfloat162_rn(make_float2(acc[mt][nt][2], acc[mt][nt][3]));
            *reinterpret_cast<uint32_t*>(g_V + (size_t)gm * 2048 + gn) = *reinterpret_cast<uint32_t*>(&v0);
            *reinterpret_cast<uint32_t*>(g_V + (size_t)(gm + 8) * 2048 + gn) = *reinterpret_cast<uint32_t*>(&v1);
        }
    }
}

// ======================= K3a: layer 0 ============================================
// h1[s][j] = relu(b0[j] + V[32*128+j][s] + sum_i (W0[j,i] + V[j*32+i][s]) * x[s,i])
__global__ __launch_bounds__(512)
void k3a(const float* __restrict__ x, const float* __restrict__ W0, const float* __restrict__ b0)
{
    __shared__ __align__(16) float xT[32 * 128];
    __shared__ float sW0[16 * 32];
    const int tid = threadIdx.x, w = tid >> 5, lane = tid & 31;
    const int s0 = blockIdx.x * 128, jg = blockIdx.y;

    for (int t = tid; t < 4096; t += 512) {
        int sl = t >> 5, i = t & 31;
        xT[i * 128 + sl] = x[(s0 + sl) * 32 + i];
    }
    if (tid < 512) sW0[tid] = W0[jg * 512 + tid];
    __syncthreads();

    const int j = jg * 16 + w;
    const __nv_bfloat16* vp = g_V + (size_t)(j * 32) * 2048 + s0 + 4 * lane;
    const float* w0r = sW0 + w * 32;
    float a0 = 0.f, a1 = 0.f, a2 = 0.f, a3 = 0.f;
#pragma unroll 4
    for (int i = 0; i < 32; i++) {
        uint2 vv = *reinterpret_cast<const uint2*>(vp + (size_t)i * 2048);
        float2 vlo = __bfloat1622float2(*reinterpret_cast<__nv_bfloat162*>(&vv.x));
        float2 vhi = __bfloat1622float2(*reinterpret_cast<__nv_bfloat162*>(&vv.y));
        float wc = w0r[i];
        float4 xv = *reinterpret_cast<const float4*>(xT + i * 128 + 4 * lane);
        a0 = fmaf(wc + vlo.x, xv.x, a0);
        a1 = fmaf(wc + vlo.y, xv.y, a1);
        a2 = fmaf(wc + vhi.x, xv.z, a2);
        a3 = fmaf(wc + vhi.y, xv.w, a3);
    }
    uint2 bv = *reinterpret_cast<const uint2*>(g_V + (size_t)(32 * 128 + j) * 2048 + s0 + 4 * lane);
    float2 blo = __bfloat1622float2(*reinterpret_cast<__nv_bfloat162*>(&bv.x));
    float2 bhi = __bfloat1622float2(*reinterpret_cast<__nv_bfloat162*>(&bv.y));
    float bb = b0[j];
    float4 o;
    o.x = fmaxf(a0 + bb + blo.x, 0.f);
    o.y = fmaxf(a1 + bb + blo.y, 0.f);
    o.z = fmaxf(a2 + bb + bhi.x, 0.f);
    o.w = fmaxf(a3 + bb + bhi.y, 0.f);
    *reinterpret_cast<float4*>(g_H1T + j * 2048 + s0 + 4 * lane) = o;
}

// ======================= K3b: layer 1 ============================================
__global__ __launch_bounds__(512)
void k3b(const float* __restrict__ W1, const float* __restrict__ b1)
{
    extern __shared__ float sm[];
    float* sh1 = sm;            // 128 x 128
    float* sW1 = sm + 16384;    // 16 x 128
    const int tid = threadIdx.x, w = tid >> 5, lane = tid & 31;
    const int s0 = blockIdx.x * 128, jg = blockIdx.y;

    const float4* src = reinterpret_cast<const float4*>(g_H1T);
    float4* d4 = reinterpret_cast<float4*>(sh1);
    for (int t = tid; t < 4096; t += 512) {
        int e = t >> 5, c = t & 31;
        d4[e * 32 + c] = src[e * 512 + (s0 >> 2) + c];
    }
    for (int t = tid; t < 2048; t += 512) sW1[t] = W1[jg * 2048 + t];
    __syncthreads();

    const int j = jg * 16 + w;
    const __nv_bfloat16* vp = g_V + (size_t)((33 + j) * 128) * 2048 + s0 + 4 * lane;
    const float* w1r = sW1 + w * 128;
    float a0 = 0.f, a1 = 0.f, a2 = 0.f, a3 = 0.f;
#pragma unroll 4
    for (int e = 0; e < 128; e++) {
        uint2 vv = *reinterpret_cast<const uint2*>(vp + (size_t)e * 2048);
        float2 vlo = __bfloat1622float2(*reinterpret_cast<__nv_bfloat162*>(&vv.x));
        float2 vhi = __bfloat1622float2(*reinterpret_cast<__nv_bfloat162*>(&vv.y));
        float wc = w1r[e];
        float4 h = *reinterpret_cast<const float4*>(sh1 + e * 128 + 4 * lane);
        a0 = fmaf(wc + vlo.x, h.x, a0);
        a1 = fmaf(wc + vlo.y, h.y, a1);
        a2 = fmaf(wc + vhi.x, h.z, a2);
        a3 = fmaf(wc + vhi.y, h.w, a3);
    }
    uint2 bv = *reinterpret_cast<const uint2*>(g_V + (size_t)(161 * 128 + j) * 2048 + s0 + 4 * lane);
    float2 blo = __bfloat1622float2(*reinterpret_cast<__nv_bfloat162*>(&bv.x));
    float2 bhi = __bfloat1622float2(*reinterpret_cast<__nv_bfloat162*>(&bv.y));
    float bb = b1[j];
    float4 o;
    o.x = fmaxf(a0 + bb + blo.x, 0.f);
    o.y = fmaxf(a1 + bb + blo.y, 0.f);
    o.z = fmaxf(a2 + bb + bhi.x, 0.f);
    o.w = fmaxf(a3 + bb + bhi.y, 0.f);
    *reinterpret_cast<float4*>(g_H2T + j * 2048 + s0 + 4 * lane) = o;
}

// ======================= K3c: layer 2 ============================================
__global__ __launch_bounds__(512)
void k3c(const float* __restrict__ W2, const float* __restrict__ b2, float* __restrict__ out)
{
    __shared__ __align__(16) float sh2[128 * 64];
    __shared__ float sW2[16 * 128];
    const int tid = threadIdx.x, w = tid >> 5, lane = tid & 31;
    const int s0 = blockIdx.x * 64;

    const float4* src = reinterpret_cast<const float4*>(g_H2T);
    float4* d4 = reinterpret_cast<float4*>(sh2);
    for (int t = tid; t < 2048; t += 512) {
        int e = t >> 4, c = t & 15;
        d4[e * 16 + c] = src[e * 512 + (s0 >> 2) + c];
    }
    for (int t = tid; t < 2048; t += 512) sW2[t] = W2[t];
    __syncthreads();

    const int j = w;
    const __nv_bfloat16* vp = g_V + (size_t)((162 + j) * 128) * 2048 + s0 + 2 * lane;
    const float* w2r = sW2 + j * 128;
    float a0 = 0.f, a1 = 0.f;
#pragma unroll 4
    for (int e = 0; e < 128; e++) {
        uint32_t vv = *reinterpret_cast<const uint32_t*>(vp + (size_t)e * 2048);
        float2 v2 = __bfloat1622float2(*reinterpret_cast<__nv_bfloat162*>(&vv));
        float wc = w2r[e];
        float2 h = *reinterpret_cast<const float2*>(sh2 + e * 64 + 2 * lane);
        a0 = fmaf(wc + v2.x, h.x, a0);
        a1 = fmaf(wc + v2.y, h.y, a1);
    }
    uint32_t bv = *reinterpret_cast<const uint32_t*>(g_V + (size_t)(178 * 128 + j) * 2048 + s0 + 2 * lane);
    float2 bd = __bfloat1622float2(*reinterpret_cast<__nv_bfloat162*>(&bv));
    float bb = b2[j];
    out[(s0 + 2 * lane + 0) * 16 + j] = a0 + bb + bd.x;
    out[(s0 + 2 * lane + 1) * 16 + j] = a1 + bb + bd.y;
}

// ======================= launch ===================================================
extern "C" void kernel_launch(void* const* d_in, const int* in_sizes, int n_in,
                              void* d_out, int out_size) {
    (void)in_sizes; (void)n_in; (void)out_size;
    const float* x   = (const float*)d_in[0];
    const float* z   = (const float*)d_in[1];
    const float* W0  = (const float*)d_in[2];
    const float* b0  = (const float*)d_in[3];
    const float* W1  = (const float*)d_in[4];
    const float* b1  = (const float*)d_in[5];
    const float* W2  = (const float*)d_in[6];
    const float* b2  = (const float*)d_in[7];
    const float* ffB = (const float*)d_in[8];
    const float* ffG = (const float*)d_in[9];
    const float* ffS = (const float*)d_in[10];
    const int*   ffP = (const int*)d_in[11];
    float* out = (float*)d_out;

    static bool attr_done = false;
    if (!attr_done) {
        cudaFuncSetAttribute(k2_gemm, cudaFuncAttributeMaxDynamicSharedMemorySize, 65536);
        cudaFuncSetAttribute(k3b, cudaFuncAttributeMaxDynamicSharedMemorySize, (16384 + 2048) * 4);
        attr_done = true;
    }

    k1_build<<<2928, 256>>>(z, ffB, ffG, ffS, ffP);
    k2_gemm<<<dim3(179, 16), 256, 65536>>>();
    k3a<<<dim3(16, 8), 512>>>(x, W0, b0);
    k3b<<<dim3(16, 8), 512, (16384 + 2048) * 4>>>(W1, b1);
    k3c<<<32, 512>>>(W2, b2, out);
}

// round 5
// speedup vs baseline: 1.3076x; 1.3076x over previous
#include <cuda_runtime.h>
#include <cuda_fp16.h>
#include <cstdint>

#define FULLMASK 0xFFFFFFFFu

// ======================= device scratch (no allocs allowed) =======================
__device__ __align__(16) __half g_Mh[179u * 128u * 128u];   // per-block linear maps, fp16
__device__ __align__(16) __half g_Zh[2048u * 128u];         // z in fp16
__device__ __align__(16) __half g_H1h[128u * 2048u];        // h1 fp16 [e][s] for KB epilogue
__device__ __align__(16) float  g_H1T[128u * 2048u];        // h1 fp32 [j][s]
__device__ __align__(16) float  g_H2T[128u * 2048u];        // h2 fp32 [j][s]
__device__ __align__(16) float  g_D0[128u * 2048u];         // layer-0 weight-delta contraction
__device__ __align__(16) float  g_D1[128u * 2048u];         // layer-1 weight-delta contraction
__device__ __align__(16) float  g_BD[3u * 128u * 2048u];    // bias deltas (blocks 32,161,178)

__device__ __forceinline__ uint32_t smem_u32(const void* p) {
    uint32_t a;
    asm("{ .reg .u64 t; cvta.to.shared.u64 t, %1; cvt.u32.u64 %0, t; }" : "=r"(a) : "l"(p));
    return a;
}

// ======================= FWHT (contiguous layout) =======================
__device__ __forceinline__ void fwht128c(float &u0, float &u1, float &u2, float &u3, int lane) {
    float a0 = u0 + u1, a1 = u0 - u1;
    float a2 = u2 + u3, a3 = u2 - u3;
    u0 = a0 + a2; u2 = a0 - a2;
    u1 = a1 + a3; u3 = a1 - a3;
#pragma unroll
    for (int m = 1; m <= 16; m <<= 1) {
        float s = (lane & m) ? -1.0f : 1.0f;
        float p0 = __shfl_xor_sync(FULLMASK, u0, m);
        float p1 = __shfl_xor_sync(FULLMASK, u1, m);
        float p2 = __shfl_xor_sync(FULLMASK, u2, m);
        float p3 = __shfl_xor_sync(FULLMASK, u3, m);
        u0 = fmaf(s, u0, p0); u1 = fmaf(s, u1, p1);
        u2 = fmaf(s, u2, p2); u3 = fmaf(s, u3, p3);
    }
}

// ======================= K1: build M rows (fp16) + convert z to fp16 ==============
// Row m of M_r = (ffS[r,m]/128) * ffB[r,:] * H( scatter_P( ffG[r,:] * H[:,m] ) )
__global__ __launch_bounds__(256)
void k1_build(const float* __restrict__ z,
              const float* __restrict__ ffB, const float* __restrict__ ffG,
              const float* __restrict__ ffS, const int* __restrict__ ffP)
{
    __shared__ __align__(16) float sstg[8][128];
    const int tid = threadIdx.x, w = tid >> 5, lane = tid & 31;

    if (blockIdx.x >= 2864) {
        int gt = (blockIdx.x - 2864) * 256 + tid;
        const float4* zf4 = reinterpret_cast<const float4*>(z);
        uint2* zb2 = reinterpret_cast<uint2*>(g_Zh);
#pragma unroll
        for (int it = 0; it < 4; it++) {
            int i = gt * 4 + it;
            float4 v = zf4[i];
            __half2 lo = __floats2half2_rn(v.x, v.y);
            __half2 hi = __floats2half2_rn(v.z, v.w);
            uint2 o;
            o.x = *reinterpret_cast<uint32_t*>(&lo);
            o.y = *reinterpret_cast<uint32_t*>(&hi);
            zb2[i] = o;
        }
        return;
    }

    const int rowid = blockIdx.x * 8 + w;       // 0..22911
    const int r = rowid >> 7, m = rowid & 127;
    const int o = r * 128;

    float4 g4 = reinterpret_cast<const float4*>(ffG + o)[lane];
    float4 b4 = reinterpret_cast<const float4*>(ffB + o)[lane];
    int4   p4 = reinterpret_cast<const int4*>(ffP + o)[lane];
    float  sm = ffS[o + m] * (1.0f / 128.0f);

    int e = lane << 2;
    float t0 = (__popc((e + 0) & m) & 1) ? -g4.x : g4.x;
    float t1 = (__popc((e + 1) & m) & 1) ? -g4.y : g4.y;
    float t2 = (__popc((e + 2) & m) & 1) ? -g4.z : g4.z;
    float t3 = (__popc((e + 3) & m) & 1) ? -g4.w : g4.w;

    float* stg = sstg[w];
    stg[p4.x] = t0; stg[p4.y] = t1; stg[p4.z] = t2; stg[p4.w] = t3;
    __syncwarp();
    float4 u = *reinterpret_cast<float4*>(stg + e);
    fwht128c(u.x, u.y, u.z, u.w, lane);

    __half2 lo = __floats2half2_rn(sm * b4.x * u.x, sm * b4.y * u.y);
    __half2 hi = __floats2half2_rn(sm * b4.z * u.z, sm * b4.w * u.w);
    uint2 ov;
    ov.x = *reinterpret_cast<uint32_t*>(&lo);
    ov.y = *reinterpret_cast<uint32_t*>(&hi);
    reinterpret_cast<uint2*>(g_Mh + (size_t)rowid * 128)[lane] = ov;
}

// ======================= shared MMA machinery (validated in R4) ===================
// smem tile: 128 rows x 256B, 16B chunks XOR-swizzled: chunk ch at ch^(row&7)
#define SWZ(row, ch) ((uint32_t)((row) * 256 + (((ch) ^ ((row) & 7)) << 4)))

__device__ __forceinline__ void ldmx4(uint32_t &r0, uint32_t &r1, uint32_t &r2, uint32_t &r3, uint32_t a) {
    asm volatile("ldmatrix.sync.aligned.m8n8.x4.shared.b16 {%0,%1,%2,%3}, [%4];"
                 : "=r"(r0), "=r"(r1), "=r"(r2), "=r"(r3) : "r"(a));
}
__device__ __forceinline__ void ldmx2(uint32_t &r0, uint32_t &r1, uint32_t a) {
    asm volatile("ldmatrix.sync.aligned.m8n8.x2.shared.b16 {%0,%1}, [%2];"
                 : "=r"(r0), "=r"(r1) : "r"(a));
}
__device__ __forceinline__ void mma_f16(float c[4], const uint32_t a[4], const uint32_t b[2]) {
    asm volatile(
        "mma.sync.aligned.m16n8k16.row.col.f32.f16.f16.f32 "
        "{%0,%1,%2,%3}, {%4,%5,%6,%7}, {%8,%9}, {%0,%1,%2,%3};"
        : "+f"(c[0]), "+f"(c[1]), "+f"(c[2]), "+f"(c[3])
        : "r"(a[0]), "r"(a[1]), "r"(a[2]), "r"(a[3]), "r"(b[0]), "r"(b[1]));
}

// Fill a 32KB tile (128 rows x 128 fp16) into swizzled smem; 256 threads.
__device__ __forceinline__ void fill_tile(char* sm, const uint4* __restrict__ src, int tid) {
#pragma unroll
    for (int it = 0; it < 8; it++) {
        int c = it * 256 + tid;
        int row = c >> 4, ch = c & 15;
        *reinterpret_cast<uint4*>(sm + SWZ(row, ch)) = src[c];
    }
}

// 128x128x128 MMA: acc[mt][nt][q]:
//   e (row of M)  = wm*64 + mt*16 + (lane>>2) + 8*(q>>1)
//   s (sample)    = wn*32 + nt*8 + 2*(lane&3) + (q&1)
__device__ __forceinline__ void mma_tile(const char* smA, const char* smB,
                                         int lane, int wm, int wn, float acc[4][4][4]) {
    uint32_t sbA = smem_u32(smA), sbB = smem_u32(smB);
    const int mbase = wm * 64, nbase = wn * 32;
    const int arow = lane & 15, ach = lane >> 4;
    const int brow = lane & 7,  bch = (lane >> 3) & 1;
#pragma unroll
    for (int mt = 0; mt < 4; mt++)
#pragma unroll
        for (int nt = 0; nt < 4; nt++)
#pragma unroll
            for (int q = 0; q < 4; q++) acc[mt][nt][q] = 0.0f;
#pragma unroll
    for (int ks = 0; ks < 8; ks++) {
        const int k0c = ks * 2;
        uint32_t a[4][4], b[4][2];
#pragma unroll
        for (int mt = 0; mt < 4; mt++)
            ldmx4(a[mt][0], a[mt][1], a[mt][2], a[mt][3],
                  sbA + SWZ(mbase + mt * 16 + arow, k0c + ach));
#pragma unroll
        for (int nt = 0; nt < 4; nt++)
            ldmx2(b[nt][0], b[nt][1], sbB + SWZ(nbase + nt * 8 + brow, k0c + bch));
#pragma unroll
        for (int mt = 0; mt < 4; mt++)
#pragma unroll
            for (int nt = 0; nt < 4; nt++)
                mma_f16(acc[mt][nt], a[mt], b[nt]);
    }
}

template <int N>
__device__ __forceinline__ void red3(float* p) {
#pragma unroll
    for (int m = 4; m <= 16; m <<= 1)
#pragma unroll
        for (int i = 0; i < N; i++) p[i] += __shfl_xor_sync(FULLMASK, p[i], m);
}

// ======================= KA: layer-0 weight blocks + all bias blocks ==============
// grid (35, 16): t<32 -> block t (W0 rows 4t..4t+3), t=32/33/34 -> blocks 32/161/178.
__global__ __launch_bounds__(256, 2)
void kA(const float* __restrict__ x)
{
    extern __shared__ char sm[];
    char* smA = sm;
    char* smB = sm + 32768;
    float* xsm = reinterpret_cast<float*>(sm + 65536);   // [128 s][32 i]
    const int tid = threadIdx.x, w = tid >> 5, lane = tid & 31;
    const int wm = w & 1, wn = w >> 1;
    const int t = blockIdx.x;
    const int s0 = blockIdx.y * 128;
    const int r = (t < 32) ? t : (t == 32 ? 32 : (t == 33 ? 161 : 178));

    fill_tile(smA, reinterpret_cast<const uint4*>(g_Mh + (size_t)r * 16384), tid);
    fill_tile(smB, reinterpret_cast<const uint4*>(g_Zh + (size_t)s0 * 128), tid);
    if (t < 32) {
        for (int c = tid; c < 4096; c += 256) {
            int s = c >> 5, i = c & 31;
            xsm[s * 32 + i] = x[(s0 + s) * 32 + i];
        }
    }
    __syncthreads();

    float acc[4][4][4];
    mma_tile(smA, smB, lane, wm, wn, acc);

    if (t < 32) {
        // delta0[s, 4t + wm*2 + pl] = sum_i V[32p+i][s] * x[s,i];  i = e & 31, pl = mt>>1
        float pp[16];
#pragma unroll
        for (int i = 0; i < 16; i++) pp[i] = 0.0f;
#pragma unroll
        for (int mt = 0; mt < 4; mt++) {
            const int pl = mt >> 1;
#pragma unroll
            for (int qh = 0; qh < 2; qh++) {
                const int e = wm * 64 + mt * 16 + (lane >> 2) + 8 * qh;
                const int i = e & 31;
#pragma unroll
                for (int nt = 0; nt < 4; nt++) {
                    const int sb = wn * 32 + nt * 8 + 2 * (lane & 3);
                    pp[pl * 8 + nt * 2 + 0] += acc[mt][nt][2 * qh + 0] * xsm[(sb + 0) * 32 + i];
                    pp[pl * 8 + nt * 2 + 1] += acc[mt][nt][2 * qh + 1] * xsm[(sb + 1) * 32 + i];
                }
            }
        }
        red3<16>(pp);
        if (lane < 4) {
#pragma unroll
            for (int pl = 0; pl < 2; pl++)
#pragma unroll
                for (int nt = 0; nt < 4; nt++)
#pragma unroll
                    for (int q01 = 0; q01 < 2; q01++) {
                        int s = wn * 32 + nt * 8 + 2 * lane + q01;
                        int j = 4 * t + wm * 2 + pl;
                        g_D0[(size_t)j * 2048 + s0 + s] = pp[pl * 8 + nt * 2 + q01];
                    }
        }
    } else {
        // bias blocks: write V rows directly (fp32)
        float* dst = g_BD + (size_t)(t - 32) * 128 * 2048;
#pragma unroll
        for (int mt = 0; mt < 4; mt++)
#pragma unroll
            for (int qh = 0; qh < 2; qh++) {
                const int e = wm * 64 + mt * 16 + (lane >> 2) + 8 * qh;
#pragma unroll
                for (int nt = 0; nt < 4; nt++) {
                    const int s = wn * 32 + nt * 8 + 2 * (lane & 3);
                    *reinterpret_cast<float2*>(dst + (size_t)e * 2048 + s0 + s) =
                        make_float2(acc[mt][nt][2 * qh + 0], acc[mt][nt][2 * qh + 1]);
                }
            }
    }
}

// ======================= h1fin: h1 = relu(W0 x + b0 + bd0 + d0) ===================
__global__ __launch_bounds__(256)
void h1fin(const float* __restrict__ x, const float* __restrict__ W0, const float* __restrict__ b0)
{
    __shared__ float xsm[128 * 32];
    __shared__ float w0sm[16 * 32];
    const int tid = threadIdx.x;
    const int s0 = blockIdx.x * 128, jg = blockIdx.y;

    for (int c = tid; c < 4096; c += 256) {
        int s = c >> 5, i = c & 31;
        xsm[s * 32 + i] = x[(s0 + s) * 32 + i];
    }
    for (int c = tid; c < 512; c += 256) w0sm[c] = W0[jg * 512 + c];
    __syncthreads();

    const int s = tid & 127, jh = tid >> 7;
#pragma unroll
    for (int jj = 0; jj < 8; jj++) {
        const int jl = jh * 8 + jj, j = jg * 16 + jl;
        float a = b0[j] + g_BD[(size_t)j * 2048 + s0 + s] + g_D0[(size_t)j * 2048 + s0 + s];
#pragma unroll
        for (int i = 0; i < 32; i++) a = fmaf(w0sm[jl * 32 + i], xsm[s * 32 + i], a);
        a = fmaxf(a, 0.0f);
        g_H1T[(size_t)j * 2048 + s0 + s] = a;
        g_H1h[(size_t)j * 2048 + s0 + s] = __float2half(a);
    }
}

// ======================= KB: layer-1 weight blocks (33..160) ======================
// grid (16 j-groups, 16 s-tiles); each CTA loops over 8 blocks sharing z + h1 tiles.
__global__ __launch_bounds__(256, 2)
void kB()
{
    extern __shared__ char sm[];
    char* smA = sm;
    char* smB = sm + 32768;
    __half* h1sm = reinterpret_cast<__half*>(sm + 65536);   // [128 e][128 s]
    float* sd = reinterpret_cast<float*>(sm + 65536 + 32768); // [2][128]
    const int tid = threadIdx.x, w = tid >> 5, lane = tid & 31;
    const int wm = w & 1, wn = w >> 1;
    const int jg = blockIdx.x;
    const int s0 = blockIdx.y * 128;

    fill_tile(smB, reinterpret_cast<const uint4*>(g_Zh + (size_t)s0 * 128), tid);
    for (int c = tid; c < 2048; c += 256) {   // h1 tile: 2048 uint4
        int e = c >> 4, ch = c & 15;
        reinterpret_cast<uint4*>(h1sm)[c] =
            *reinterpret_cast<const uint4*>(g_H1h + (size_t)e * 2048 + s0 + ch * 8);
    }

#pragma unroll 1
    for (int b = 0; b < 8; b++) {
        const int j = jg * 8 + b;
        fill_tile(smA, reinterpret_cast<const uint4*>(g_Mh + (size_t)(33 + j) * 16384), tid);
        __syncthreads();

        float acc[4][4][4];
        mma_tile(smA, smB, lane, wm, wn, acc);

        // delta1_partial[s] = sum_e V[e][s] * h1[e][s]
        float pb[8];
#pragma unroll
        for (int i = 0; i < 8; i++) pb[i] = 0.0f;
#pragma unroll
        for (int mt = 0; mt < 4; mt++)
#pragma unroll
            for (int qh = 0; qh < 2; qh++) {
                const int e = wm * 64 + mt * 16 + (lane >> 2) + 8 * qh;
                const __half2* hrow = reinterpret_cast<const __half2*>(h1sm + e * 128);
#pragma unroll
                for (int nt = 0; nt < 4; nt++) {
                    const int sb = wn * 32 + nt * 8 + 2 * (lane & 3);
                    float2 hv = __half22float2(hrow[sb >> 1]);
                    pb[nt * 2 + 0] += acc[mt][nt][2 * qh + 0] * hv.x;
                    pb[nt * 2 + 1] += acc[mt][nt][2 * qh + 1] * hv.y;
                }
            }
        red3<8>(pb);
        if (lane < 4) {
#pragma unroll
            for (int nt = 0; nt < 4; nt++)
#pragma unroll
                for (int q01 = 0; q01 < 2; q01++)
                    sd[wm * 128 + wn * 32 + nt * 8 + 2 * lane + q01] = pb[nt * 2 + q01];
        }
        __syncthreads();
        if (tid < 128)
            g_D1[(size_t)j * 2048 + s0 + tid] = sd[tid] + sd[128 + tid];
    }
}

// ======================= h2fin: h2 = relu(W1 h1 + b1 + bd1 + d1) ==================
__global__ __launch_bounds__(256)
void h2fin(const float* __restrict__ W1, const float* __restrict__ b1)
{
    extern __shared__ float smf[];
    float* h1sm = smf;            // [128 e][128 s]
    float* w1sm = smf + 16384;    // [16][128]
    const int tid = threadIdx.x;
    const int s0 = blockIdx.x * 128, jg = blockIdx.y;

    for (int c = tid; c < 4096; c += 256) {
        int e = c >> 5, ch = c & 31;
        reinterpret_cast<float4*>(h1sm)[c] =
            *reinterpret_cast<const float4*>(g_H1T + (size_t)e * 2048 + s0 + ch * 4);
    }
    for (int c = tid; c < 2048; c += 256) w1sm[c] = W1[jg * 2048 + c];
    __syncthreads();

    const int s = tid & 127, jh = tid >> 7;
    float a[8];
#pragma unroll
    for (int jj = 0; jj < 8; jj++) {
        const int j = jg * 16 + jh * 8 + jj;
        a[jj] = b1[j] + g_BD[(size_t)(128 + j) * 2048 + s0 + s] + g_D1[(size_t)j * 2048 + s0 + s];
    }
#pragma unroll 4
    for (int e = 0; e < 128; e++) {
        const float h = h1sm[e * 128 + s];
#pragma unroll
        for (int jj = 0; jj < 8; jj++)
            a[jj] = fmaf(w1sm[(jh * 8 + jj) * 128 + e], h, a[jj]);
    }
#pragma unroll
    for (int jj = 0; jj < 8; jj++) {
        const int j = jg * 16 + jh * 8 + jj;
        g_H2T[(size_t)j * 2048 + s0 + s] = fmaxf(a[jj], 0.0f);
    }
}

// ======================= KC: layer-2 blocks (162..177) + output ===================
// grid (16 j, 16 s-tiles): out[s,j] = b2[j] + bd2[j][s] + sum_e (W2[j,e]+V[e,s]) h2[s,e]
__global__ __launch_bounds__(256, 1)
void kC(const float* __restrict__ W2, const float* __restrict__ b2, float* __restrict__ out)
{
    extern __shared__ char sm[];
    char* smA = sm;
    char* smB = sm + 32768;
    float* h2sm = reinterpret_cast<float*>(sm + 65536);           // [128 e][128 s] fp32
    float* w2sm = reinterpret_cast<float*>(sm + 65536 + 65536);   // [128]
    float* sd = w2sm + 128;                                       // [2][128]
    const int tid = threadIdx.x, w = tid >> 5, lane = tid & 31;
    const int wm = w & 1, wn = w >> 1;
    const int jj = blockIdx.x;
    const int s0 = blockIdx.y * 128;

    fill_tile(smA, reinterpret_cast<const uint4*>(g_Mh + (size_t)(162 + jj) * 16384), tid);
    fill_tile(smB, reinterpret_cast<const uint4*>(g_Zh + (size_t)s0 * 128), tid);
    for (int c = tid; c < 4096; c += 256) {
        int e = c >> 5, ch = c & 31;
        reinterpret_cast<float4*>(h2sm)[c] =
            *reinterpret_cast<const float4*>(g_H2T + (size_t)e * 2048 + s0 + ch * 4);
    }
    if (tid < 128) w2sm[tid] = W2[jj * 128 + tid];
    __syncthreads();

    float acc[4][4][4];
    mma_tile(smA, smB, lane, wm, wn, acc);

    float pb[8];
#pragma unroll
    for (int i = 0; i < 8; i++) pb[i] = 0.0f;
#pragma unroll
    for (int mt = 0; mt < 4; mt++)
#pragma unroll
        for (int qh = 0; qh < 2; qh++) {
            const int e = wm * 64 + mt * 16 + (lane >> 2) + 8 * qh;
            const float wv = w2sm[e];
#pragma unroll
            for (int nt = 0; nt < 4; nt++) {
                const int sb = wn * 32 + nt * 8 + 2 * (lane & 3);
                pb[nt * 2 + 0] += (acc[mt][nt][2 * qh + 0] + wv) * h2sm[e * 128 + sb + 0];
                pb[nt * 2 + 1] += (acc[mt][nt][2 * qh + 1] + wv) * h2sm[e * 128 + sb + 1];
            }
        }
    red3<8>(pb);
    if (lane < 4) {
#pragma unroll
        for (int nt = 0; nt < 4; nt++)
#pragma unroll
            for (int q01 = 0; q01 < 2; q01++)
                sd[wm * 128 + wn * 32 + nt * 8 + 2 * lane + q01] = pb[nt * 2 + q01];
    }
    __syncthreads();
    if (tid < 128)
        out[(size_t)(s0 + tid) * 16 + jj] =
            b2[jj] + g_BD[(size_t)(256 + jj) * 2048 + s0 + tid] + sd[tid] + sd[128 + tid];
}

// ======================= launch ===================================================
extern "C" void kernel_launch(void* const* d_in, const int* in_sizes, int n_in,
                              void* d_out, int out_size) {
    (void)in_sizes; (void)n_in; (void)out_size;
    const float* x   = (const float*)d_in[0];
    const float* z   = (const float*)d_in[1];
    const float* W0  = (const float*)d_in[2];
    const float* b0  = (const float*)d_in[3];
    const float* W1  = (const float*)d_in[4];
    const float* b1  = (const float*)d_in[5];
    const float* W2  = (const float*)d_in[6];
    const float* b2  = (const float*)d_in[7];
    const float* ffB = (const float*)d_in[8];
    const float* ffG = (const float*)d_in[9];
    const float* ffS = (const float*)d_in[10];
    const int*   ffP = (const int*)d_in[11];
    float* out = (float*)d_out;

    cudaFuncSetAttribute(kA, cudaFuncAttributeMaxDynamicSharedMemorySize, 81920);
    cudaFuncSetAttribute(kB, cudaFuncAttributeMaxDynamicSharedMemorySize, 99328);
    cudaFuncSetAttribute(h2fin, cudaFuncAttributeMaxDynamicSharedMemorySize, 73728);
    cudaFuncSetAttribute(kC, cudaFuncAttributeMaxDynamicSharedMemorySize, 132608);

    k1_build<<<2928, 256>>>(z, ffB, ffG, ffS, ffP);
    kA<<<dim3(35, 16), 256, 81920>>>(x);
    h1fin<<<dim3(16, 8), 256>>>(x, W0, b0);
    kB<<<dim3(16, 16), 256, 99328>>>();
    h2fin<<<dim3(16, 8), 256, 73728>>>(W1, b1);
    kC<<<dim3(16, 16), 256, 132608>>>(W2, b2, out);
}

// round 6
// speedup vs baseline: 1.3945x; 1.0665x over previous
#include <cuda_runtime.h>
#include <cuda_fp16.h>
#include <cstdint>

#define FULLMASK 0xFFFFFFFFu

// ======================= device scratch (no allocs allowed) =======================
__device__ __align__(16) __half g_Mh[179u * 128u * 128u];   // per-block linear maps, fp16
__device__ __align__(16) __half g_Zh[2048u * 128u];         // z in fp16
__device__ __align__(16) float  g_H1T[128u * 2048u];        // h1 fp32 [j][s]
__device__ __align__(16) float  g_H2T[128u * 2048u];        // h2 fp32 [j][s]
__device__ __align__(16) float  g_D0[128u * 2048u];         // layer-0 weight-delta contraction
__device__ __align__(16) float  g_D1P[8u * 128u * 2048u];   // layer-1 delta partials (K-split)
__device__ __align__(16) float  g_BD[3u * 128u * 2048u];    // bias deltas (blocks 32,161,178)

__device__ __forceinline__ uint32_t smem_u32(const void* p) {
    uint32_t a;
    asm("{ .reg .u64 t; cvta.to.shared.u64 t, %1; cvt.u32.u64 %0, t; }" : "=r"(a) : "l"(p));
    return a;
}

// ======================= FWHT (contiguous layout) =======================
__device__ __forceinline__ void fwht128c(float &u0, float &u1, float &u2, float &u3, int lane) {
    float a0 = u0 + u1, a1 = u0 - u1;
    float a2 = u2 + u3, a3 = u2 - u3;
    u0 = a0 + a2; u2 = a0 - a2;
    u1 = a1 + a3; u3 = a1 - a3;
#pragma unroll
    for (int m = 1; m <= 16; m <<= 1) {
        float s = (lane & m) ? -1.0f : 1.0f;
        float p0 = __shfl_xor_sync(FULLMASK, u0, m);
        float p1 = __shfl_xor_sync(FULLMASK, u1, m);
        float p2 = __shfl_xor_sync(FULLMASK, u2, m);
        float p3 = __shfl_xor_sync(FULLMASK, u3, m);
        u0 = fmaf(s, u0, p0); u1 = fmaf(s, u1, p1);
        u2 = fmaf(s, u2, p2); u3 = fmaf(s, u3, p3);
    }
}

// ======================= K1: build M rows (fp16) + convert z to fp16 ==============
__global__ __launch_bounds__(256)
void k1_build(const float* __restrict__ z,
              const float* __restrict__ ffB, const float* __restrict__ ffG,
              const float* __restrict__ ffS, const int* __restrict__ ffP)
{
    __shared__ __align__(16) float sstg[8][128];
    const int tid = threadIdx.x, w = tid >> 5, lane = tid & 31;

    if (blockIdx.x >= 2864) {
        int gt = (blockIdx.x - 2864) * 256 + tid;
        const float4* zf4 = reinterpret_cast<const float4*>(z);
        uint2* zb2 = reinterpret_cast<uint2*>(g_Zh);
#pragma unroll
        for (int it = 0; it < 4; it++) {
            int i = gt * 4 + it;
            float4 v = zf4[i];
            __half2 lo = __floats2half2_rn(v.x, v.y);
            __half2 hi = __floats2half2_rn(v.z, v.w);
            uint2 o;
            o.x = *reinterpret_cast<uint32_t*>(&lo);
            o.y = *reinterpret_cast<uint32_t*>(&hi);
            zb2[i] = o;
        }
        return;
    }

    const int rowid = blockIdx.x * 8 + w;       // 0..22911
    const int r = rowid >> 7, m = rowid & 127;
    const int o = r * 128;

    float4 g4 = reinterpret_cast<const float4*>(ffG + o)[lane];
    float4 b4 = reinterpret_cast<const float4*>(ffB + o)[lane];
    int4   p4 = reinterpret_cast<const int4*>(ffP + o)[lane];
    float  sm = ffS[o + m] * (1.0f / 128.0f);

    int e = lane << 2;
    float t0 = (__popc((e + 0) & m) & 1) ? -g4.x : g4.x;
    float t1 = (__popc((e + 1) & m) & 1) ? -g4.y : g4.y;
    float t2 = (__popc((e + 2) & m) & 1) ? -g4.z : g4.z;
    float t3 = (__popc((e + 3) & m) & 1) ? -g4.w : g4.w;

    float* stg = sstg[w];
    stg[p4.x] = t0; stg[p4.y] = t1; stg[p4.z] = t2; stg[p4.w] = t3;
    __syncwarp();
    float4 u = *reinterpret_cast<float4*>(stg + e);
    fwht128c(u.x, u.y, u.z, u.w, lane);

    __half2 lo = __floats2half2_rn(sm * b4.x * u.x, sm * b4.y * u.y);
    __half2 hi = __floats2half2_rn(sm * b4.z * u.z, sm * b4.w * u.w);
    uint2 ov;
    ov.x = *reinterpret_cast<uint32_t*>(&lo);
    ov.y = *reinterpret_cast<uint32_t*>(&hi);
    reinterpret_cast<uint2*>(g_Mh + (size_t)rowid * 128)[lane] = ov;
}

// ======================= shared MMA machinery =====================================
#define SWZ(row, ch) ((uint32_t)((row) * 256 + (((ch) ^ ((row) & 7)) << 4)))

__device__ __forceinline__ void ldmx4(uint32_t &r0, uint32_t &r1, uint32_t &r2, uint32_t &r3, uint32_t a) {
    asm volatile("ldmatrix.sync.aligned.m8n8.x4.shared.b16 {%0,%1,%2,%3}, [%4];"
                 : "=r"(r0), "=r"(r1), "=r"(r2), "=r"(r3) : "r"(a));
}
__device__ __forceinline__ void ldmx2(uint32_t &r0, uint32_t &r1, uint32_t a) {
    asm volatile("ldmatrix.sync.aligned.m8n8.x2.shared.b16 {%0,%1}, [%2];"
                 : "=r"(r0), "=r"(r1) : "r"(a));
}
__device__ __forceinline__ void mma_f16(float c[4], const uint32_t a[4], const uint32_t b[2]) {
    asm volatile(
        "mma.sync.aligned.m16n8k16.row.col.f32.f16.f16.f32 "
        "{%0,%1,%2,%3}, {%4,%5,%6,%7}, {%8,%9}, {%0,%1,%2,%3};"
        : "+f"(c[0]), "+f"(c[1]), "+f"(c[2]), "+f"(c[3])
        : "r"(a[0]), "r"(a[1]), "r"(a[2]), "r"(a[3]), "r"(b[0]), "r"(b[1]));
}

__device__ __forceinline__ void fill_tile(char* sm, const uint4* __restrict__ src, int tid) {
#pragma unroll
    for (int it = 0; it < 8; it++) {
        int c = it * 256 + tid;
        int row = c >> 4, ch = c & 15;
        *reinterpret_cast<uint4*>(sm + SWZ(row, ch)) = src[c];
    }
}

// accumulate into acc (no zeroing)
__device__ __forceinline__ void mma_tile_acc(const char* smA, const char* smB,
                                             int lane, int wm, int wn, float acc[4][4][4]) {
    uint32_t sbA = smem_u32(smA), sbB = smem_u32(smB);
    const int mbase = wm * 64, nbase = wn * 32;
    const int arow = lane & 15, ach = lane >> 4;
    const int brow = lane & 7,  bch = (lane >> 3) & 1;
#pragma unroll
    for (int ks = 0; ks < 8; ks++) {
        const int k0c = ks * 2;
        uint32_t a[4][4], b[4][2];
#pragma unroll
        for (int mt = 0; mt < 4; mt++)
            ldmx4(a[mt][0], a[mt][1], a[mt][2], a[mt][3],
                  sbA + SWZ(mbase + mt * 16 + arow, k0c + ach));
#pragma unroll
        for (int nt = 0; nt < 4; nt++)
            ldmx2(b[nt][0], b[nt][1], sbB + SWZ(nbase + nt * 8 + brow, k0c + bch));
#pragma unroll
        for (int mt = 0; mt < 4; mt++)
#pragma unroll
            for (int nt = 0; nt < 4; nt++)
                mma_f16(acc[mt][nt], a[mt], b[nt]);
    }
}

__device__ __forceinline__ void mma_tile(const char* smA, const char* smB,
                                         int lane, int wm, int wn, float acc[4][4][4]) {
#pragma unroll
    for (int mt = 0; mt < 4; mt++)
#pragma unroll
        for (int nt = 0; nt < 4; nt++)
#pragma unroll
            for (int q = 0; q < 4; q++) acc[mt][nt][q] = 0.0f;
    mma_tile_acc(smA, smB, lane, wm, wn, acc);
}

template <int N>
__device__ __forceinline__ void red3(float* p) {
#pragma unroll
    for (int m = 4; m <= 16; m <<= 1)
#pragma unroll
        for (int i = 0; i < N; i++) p[i] += __shfl_xor_sync(FULLMASK, p[i], m);
}

// ======================= KA: layer-0 weight blocks + all bias blocks ==============
__global__ __launch_bounds__(256, 2)
void kA(const float* __restrict__ x)
{
    extern __shared__ char sm[];
    char* smA = sm;
    char* smB = sm + 32768;
    float* xsm = reinterpret_cast<float*>(sm + 65536);   // [128 s][32 i]
    const int tid = threadIdx.x, w = tid >> 5, lane = tid & 31;
    const int wm = w & 1, wn = w >> 1;
    const int t = blockIdx.x;
    const int s0 = blockIdx.y * 128;
    const int r = (t < 32) ? t : (t == 32 ? 32 : (t == 33 ? 161 : 178));

    fill_tile(smA, reinterpret_cast<const uint4*>(g_Mh + (size_t)r * 16384), tid);
    fill_tile(smB, reinterpret_cast<const uint4*>(g_Zh + (size_t)s0 * 128), tid);
    if (t < 32) {
        for (int c = tid; c < 4096; c += 256) {
            int s = c >> 5, i = c & 31;
            xsm[s * 32 + i] = x[(s0 + s) * 32 + i];
        }
    }
    __syncthreads();

    float acc[4][4][4];
    mma_tile(smA, smB, lane, wm, wn, acc);

    if (t < 32) {
        float pp[16];
#pragma unroll
        for (int i = 0; i < 16; i++) pp[i] = 0.0f;
#pragma unroll
        for (int mt = 0; mt < 4; mt++) {
            const int pl = mt >> 1;
#pragma unroll
            for (int qh = 0; qh < 2; qh++) {
                const int e = wm * 64 + mt * 16 + (lane >> 2) + 8 * qh;
                const int i = e & 31;
#pragma unroll
                for (int nt = 0; nt < 4; nt++) {
                    const int sb = wn * 32 + nt * 8 + 2 * (lane & 3);
                    pp[pl * 8 + nt * 2 + 0] += acc[mt][nt][2 * qh + 0] * xsm[(sb + 0) * 32 + i];
                    pp[pl * 8 + nt * 2 + 1] += acc[mt][nt][2 * qh + 1] * xsm[(sb + 1) * 32 + i];
                }
            }
        }
        red3<16>(pp);
        if (lane < 4) {
#pragma unroll
            for (int pl = 0; pl < 2; pl++)
#pragma unroll
                for (int nt = 0; nt < 4; nt++)
#pragma unroll
                    for (int q01 = 0; q01 < 2; q01++) {
                        int s = wn * 32 + nt * 8 + 2 * lane + q01;
                        int j = 4 * t + wm * 2 + pl;
                        g_D0[(size_t)j * 2048 + s0 + s] = pp[pl * 8 + nt * 2 + q01];
                    }
        }
    } else {
        float* dst = g_BD + (size_t)(t - 32) * 128 * 2048;
#pragma unroll
        for (int mt = 0; mt < 4; mt++)
#pragma unroll
            for (int qh = 0; qh < 2; qh++) {
                const int e = wm * 64 + mt * 16 + (lane >> 2) + 8 * qh;
#pragma unroll
                for (int nt = 0; nt < 4; nt++) {
                    const int s = wn * 32 + nt * 8 + 2 * (lane & 3);
                    *reinterpret_cast<float2*>(dst + (size_t)e * 2048 + s0 + s) =
                        make_float2(acc[mt][nt][2 * qh + 0], acc[mt][nt][2 * qh + 1]);
                }
            }
    }
}

// ======================= h1fin: h1 = relu(W0 x + b0 + bd0 + d0) ===================
__global__ __launch_bounds__(256)
void h1fin(const float* __restrict__ x, const float* __restrict__ W0, const float* __restrict__ b0)
{
    __shared__ float xsm[128 * 32];
    __shared__ float w0sm[16 * 32];
    const int tid = threadIdx.x;
    const int s0 = blockIdx.x * 128, jg = blockIdx.y;

    for (int c = tid; c < 4096; c += 256) {
        int s = c >> 5, i = c & 31;
        xsm[s * 32 + i] = x[(s0 + s) * 32 + i];
    }
    for (int c = tid; c < 512; c += 256) w0sm[c] = W0[jg * 512 + c];
    __syncthreads();

    const int s = tid & 127, jh = tid >> 7;
#pragma unroll
    for (int jj = 0; jj < 8; jj++) {
        const int jl = jh * 8 + jj, j = jg * 16 + jl;
        float a = b0[j] + g_BD[(size_t)j * 2048 + s0 + s] + g_D0[(size_t)j * 2048 + s0 + s];
#pragma unroll
        for (int i = 0; i < 32; i++) a = fmaf(w0sm[jl * 32 + i], xsm[s * 32 + i], a);
        g_H1T[(size_t)j * 2048 + s0 + s] = fmaxf(a, 0.0f);
    }
}

// ======================= KB: layer-1 deltas as dense GEMM =========================
// D1[j, s] = sum_K A[j,K] * Omega[K,s];  A = g_Mh[33..161) as [128 j][16384 K] row-major,
// Omega[(e,k), s] = h1[s,e] * z[s,k].  K-chunk 128 = one e: Omega chunk = z tile scaled
// per s-row by h1[e,s]. Grid (8 K-splits of 16 e, 16 s-tiles); acc accumulates across
// the 16 chunks; A double-buffered via cp.async; partials to g_D1P.
__global__ __launch_bounds__(256, 1)
void kB()
{
    extern __shared__ char sm[];
    char* zsm  = sm;                       // 32K z tile (swizzled)
    char* osm  = sm + 32768;               // 32K Omega tile
    char* abuf0 = sm + 65536;              // 32K A buf 0
    char* abuf1 = sm + 98304;              // 32K A buf 1
    float* h1sm = reinterpret_cast<float*>(sm + 131072);  // [16 e][128 s]
    const int tid = threadIdx.x, w = tid >> 5, lane = tid & 31;
    const int wm = w & 1, wn = w >> 1;
    const int ksp = blockIdx.x;            // K split 0..7
    const int s0 = blockIdx.y * 128;
    const int e0 = ksp * 16;

    // issue cp.async A chunk c into buf
    auto issueA = [&](int c, char* buf) {
        const int e = e0 + c;
#pragma unroll
        for (int it = 0; it < 8; it++) {
            int idx = it * 256 + tid;
            int row = idx >> 4, ch = idx & 15;
            const char* src = reinterpret_cast<const char*>(g_Mh)
                + (((size_t)(33 + row) * 16384 + (size_t)e * 128) * 2 + ch * 16);
            uint32_t dst = smem_u32(buf + SWZ(row, ch));
            asm volatile("cp.async.cg.shared.global [%0], [%1], 16;" :: "r"(dst), "l"(src));
        }
        asm volatile("cp.async.commit_group;");
    };

    issueA(0, abuf0);

    fill_tile(zsm, reinterpret_cast<const uint4*>(g_Zh + (size_t)s0 * 128), tid);
    for (int c = tid; c < 2048; c += 256) {
        int ce = c >> 7, s = c & 127;
        h1sm[ce * 128 + s] = g_H1T[(size_t)(e0 + ce) * 2048 + s0 + s];
    }
    __syncthreads();

    float acc[4][4][4];
#pragma unroll
    for (int mt = 0; mt < 4; mt++)
#pragma unroll
        for (int nt = 0; nt < 4; nt++)
#pragma unroll
            for (int q = 0; q < 4; q++) acc[mt][nt][q] = 0.0f;

#pragma unroll 1
    for (int c = 0; c < 16; c++) {
        if (c < 15) {
            issueA(c + 1, (c & 1) ? abuf0 : abuf1);
            asm volatile("cp.async.wait_group 1;");
        } else {
            asm volatile("cp.async.wait_group 0;");
        }
        // generate Omega chunk: zsm row s scaled by h1[e0+c][s]
#pragma unroll
        for (int it = 0; it < 8; it++) {
            int idx = it * 256 + tid;
            int row = idx >> 4, ch = idx & 15;
            uint4 v = *reinterpret_cast<uint4*>(zsm + SWZ(row, ch));
            __half2 hb = __float2half2_rn(h1sm[c * 128 + row]);
            __half2* hv = reinterpret_cast<__half2*>(&v);
            hv[0] = __hmul2(hv[0], hb); hv[1] = __hmul2(hv[1], hb);
            hv[2] = __hmul2(hv[2], hb); hv[3] = __hmul2(hv[3], hb);
            *reinterpret_cast<uint4*>(osm + SWZ(row, ch)) = v;
        }
        __syncthreads();
        mma_tile_acc((c & 1) ? abuf1 : abuf0, osm, lane, wm, wn, acc);
        __syncthreads();
    }

    // write partial tile [128 j][128 s] to g_D1P[ksp]
    float* dst = g_D1P + (size_t)ksp * 128 * 2048;
#pragma unroll
    for (int mt = 0; mt < 4; mt++)
#pragma unroll
        for (int qh = 0; qh < 2; qh++) {
            const int j = wm * 64 + mt * 16 + (lane >> 2) + 8 * qh;
#pragma unroll
            for (int nt = 0; nt < 4; nt++) {
                const int s = wn * 32 + nt * 8 + 2 * (lane & 3);
                *reinterpret_cast<float2*>(dst + (size_t)j * 2048 + s0 + s) =
                    make_float2(acc[mt][nt][2 * qh + 0], acc[mt][nt][2 * qh + 1]);
            }
        }
}

// ======================= h2fin: h2 = relu(W1 h1 + b1 + bd1 + sum(D1P)) ============
__global__ __launch_bounds__(256)
void h2fin(const float* __restrict__ W1, const float* __restrict__ b1)
{
    extern __shared__ float smf[];
    float* h1sm = smf;            // [128 e][128 s]
    float* w1sm = smf + 16384;    // [16][128]
    const int tid = threadIdx.x;
    const int s0 = blockIdx.x * 128, jg = blockIdx.y;

    for (int c = tid; c < 4096; c += 256) {
        int e = c >> 5, ch = c & 31;
        reinterpret_cast<float4*>(h1sm)[c] =
            *reinterpret_cast<const float4*>(g_H1T + (size_t)e * 2048 + s0 + ch * 4);
    }
    for (int c = tid; c < 2048; c += 256) w1sm[c] = W1[jg * 2048 + c];
    __syncthreads();

    const int s = tid & 127, jh = tid >> 7;
    float a[8];
#pragma unroll
    for (int jj = 0; jj < 8; jj++) {
        const int j = jg * 16 + jh * 8 + jj;
        float acc = b1[j] + g_BD[(size_t)(128 + j) * 2048 + s0 + s];
#pragma unroll
        for (int p = 0; p < 8; p++)
            acc += g_D1P[((size_t)p * 128 + j) * 2048 + s0 + s];
        a[jj] = acc;
    }
#pragma unroll 4
    for (int e = 0; e < 128; e++) {
        const float h = h1sm[e * 128 + s];
#pragma unroll
        for (int jj = 0; jj < 8; jj++)
            a[jj] = fmaf(w1sm[(jh * 8 + jj) * 128 + e], h, a[jj]);
    }
#pragma unroll
    for (int jj = 0; jj < 8; jj++) {
        const int j = jg * 16 + jh * 8 + jj;
        g_H2T[(size_t)j * 2048 + s0 + s] = fmaxf(a[jj], 0.0f);
    }
}

// ======================= KC: layer-2 blocks (162..177) + output ===================
__global__ __launch_bounds__(256, 1)
void kC(const float* __restrict__ W2, const float* __restrict__ b2, float* __restrict__ out)
{
    extern __shared__ char sm[];
    char* smA = sm;
    char* smB = sm + 32768;
    float* h2sm = reinterpret_cast<float*>(sm + 65536);           // [128 e][128 s]
    float* w2sm = reinterpret_cast<float*>(sm + 65536 + 65536);   // [128]
    float* sd = w2sm + 128;                                       // [2][128]
    const int tid = threadIdx.x, w = tid >> 5, lane = tid & 31;
    const int wm = w & 1, wn = w >> 1;
    const int jj = blockIdx.x;
    const int s0 = blockIdx.y * 128;

    fill_tile(smA, reinterpret_cast<const uint4*>(g_Mh + (size_t)(162 + jj) * 16384), tid);
    fill_tile(smB, reinterpret_cast<const uint4*>(g_Zh + (size_t)s0 * 128), tid);
    for (int c = tid; c < 4096; c += 256) {
        int e = c >> 5, ch = c & 31;
        reinterpret_cast<float4*>(h2sm)[c] =
            *reinterpret_cast<const float4*>(g_H2T + (size_t)e * 2048 + s0 + ch * 4);
    }
    if (tid < 128) w2sm[tid] = W2[jj * 128 + tid];
    __syncthreads();

    float acc[4][4][4];
    mma_tile(smA, smB, lane, wm, wn, acc);

    float pb[8];
#pragma unroll
    for (int i = 0; i < 8; i++) pb[i] = 0.0f;
#pragma unroll
    for (int mt = 0; mt < 4; mt++)
#pragma unroll
        for (int qh = 0; qh < 2; qh++) {
            const int e = wm * 64 + mt * 16 + (lane >> 2) + 8 * qh;
            const float wv = w2sm[e];
#pragma unroll
            for (int nt = 0; nt < 4; nt++) {
                const int sb = wn * 32 + nt * 8 + 2 * (lane & 3);
                pb[nt * 2 + 0] += (acc[mt][nt][2 * qh + 0] + wv) * h2sm[e * 128 + sb + 0];
                pb[nt * 2 + 1] += (acc[mt][nt][2 * qh + 1] + wv) * h2sm[e * 128 + sb + 1];
            }
        }
    red3<8>(pb);
    if (lane < 4) {
#pragma unroll
        for (int nt = 0; nt < 4; nt++)
#pragma unroll
            for (int q01 = 0; q01 < 2; q01++)
                sd[wm * 128 + wn * 32 + nt * 8 + 2 * lane + q01] = pb[nt * 2 + q01];
    }
    __syncthreads();
    if (tid < 128)
        out[(size_t)(s0 + tid) * 16 + jj] =
            b2[jj] + g_BD[(size_t)(256 + jj) * 2048 + s0 + tid] + sd[tid] + sd[128 + tid];
}

// ======================= launch ===================================================
extern "C" void kernel_launch(void* const* d_in, const int* in_sizes, int n_in,
                              void* d_out, int out_size) {
    (void)in_sizes; (void)n_in; (void)out_size;
    const float* x   = (const float*)d_in[0];
    const float* z   = (const float*)d_in[1];
    const float* W0  = (const float*)d_in[2];
    const float* b0  = (const float*)d_in[3];
    const float* W1  = (const float*)d_in[4];
    const float* b1  = (const float*)d_in[5];
    const float* W2  = (const float*)d_in[6];
    const float* b2  = (const float*)d_in[7];
    const float* ffB = (const float*)d_in[8];
    const float* ffG = (const float*)d_in[9];
    const float* ffS = (const float*)d_in[10];
    const int*   ffP = (const int*)d_in[11];
    float* out = (float*)d_out;

    cudaFuncSetAttribute(kA, cudaFuncAttributeMaxDynamicSharedMemorySize, 81920);
    cudaFuncSetAttribute(kB, cudaFuncAttributeMaxDynamicSharedMemorySize, 139264);
    cudaFuncSetAttribute(h2fin, cudaFuncAttributeMaxDynamicSharedMemorySize, 73728);
    cudaFuncSetAttribute(kC, cudaFuncAttributeMaxDynamicSharedMemorySize, 132608);

    k1_build<<<2928, 256>>>(z, ffB, ffG, ffS, ffP);
    kA<<<dim3(35, 16), 256, 81920>>>(x);
    h1fin<<<dim3(16, 8), 256>>>(x, W0, b0);
    kB<<<dim3(8, 16), 256, 139264>>>();
    h2fin<<<dim3(16, 8), 256, 73728>>>(W1, b1);
    kC<<<dim3(16, 16), 256, 132608>>>(W2, b2, out);
}